// round 5
// baseline (speedup 1.0000x reference)
#include <cuda_runtime.h>

// Problem constants (target: [B, T, L] float32)
constexpr int B_ = 32;
constexpr int T_ = 8;
constexpr int L_ = 256;
constexpr int TILE = 128;   // output quadrant per block

// source[b, l1, l2] = (1/(T*L)) * sum_t sum_n x[n] * x[n-l1] * x[n-l2],
// x[k] = 0 for k < 0.
//
// f32x2-packed version: each thread owns an 8x8 tile, accumulated as
// 4 (l1-pairs) x 8 (l2) packed f32x2 registers. fma.rn.f32x2 does 2 FMAs
// per fma-pipe issue slot (rt_SMSP=2 is the FFMA ceiling we hit before).
//
// Replicated operands ((xn,xn) and (xb,xb)) are loaded as single LDS.64
// from a DUPLICATED shared copy of the padded signal (xd[2k]=xd[2k+1]=x[k]),
// whose even indices keep 8-byte alignment — no replication MOVs.

__device__ __forceinline__ unsigned long long pack2(float lo, float hi) {
    unsigned long long r;
    asm("mov.b64 %0, {%1, %2};" : "=l"(r) : "f"(lo), "f"(hi));
    return r;
}
__device__ __forceinline__ void unpack2(unsigned long long v, float& lo, float& hi) {
    asm("mov.b64 {%0, %1}, %2;" : "=f"(lo), "=f"(hi) : "l"(v));
}
__device__ __forceinline__ void fma2(unsigned long long& d,
                                     unsigned long long a, unsigned long long b) {
    asm("fma.rn.f32x2 %0, %1, %2, %0;" : "+l"(d) : "l"(a), "l"(b));
}
__device__ __forceinline__ unsigned long long mul2(unsigned long long a,
                                                   unsigned long long b) {
    unsigned long long r;
    asm("mul.rn.f32x2 %0, %1, %2;" : "=l"(r) : "l"(a), "l"(b));
    return r;
}

__global__ __launch_bounds__(256, 1)
void bispectrum_kernel(const float* __restrict__ tgt, float* __restrict__ out)
{
    __shared__ float xs[2 * L_];                    // plain padded: [0..255]=0, [256..511]=x
    __shared__ __align__(16) float xd[4 * L_];      // duplicated padded: xd[2k]=xd[2k+1]=xs[k]

    const int b  = blockIdx.y;
    const int q  = blockIdx.x;
    const int l1_base = (q >> 1) * TILE;
    const int l2_base = (q & 1)  * TILE;

    const int tid = threadIdx.x;
    const int tx  = tid & 15;   // l2 = l2_base + tx + 16*j
    const int ty  = tid >> 4;   // l1 = l1_base + 2*ty + 32*ip + {0,1}

    const int l1off = l1_base + 2 * ty;

    unsigned long long acc2[4][8];
#pragma unroll
    for (int ip = 0; ip < 4; ip++)
#pragma unroll
        for (int j = 0; j < 8; j++) acc2[ip][j] = 0ull;

    for (int t = 0; t < T_; t++) {
        __syncthreads();
        const float v = tgt[(b * T_ + t) * L_ + tid];
        xs[tid]              = 0.0f;
        xs[L_ + tid]         = v;
        xd[2 * tid]          = 0.0f;
        xd[2 * tid + 1]      = 0.0f;
        xd[2 * (L_ + tid)]     = v;
        xd[2 * (L_ + tid) + 1] = v;
        __syncthreads();

#pragma unroll 2
        for (int n = 0; n < L_; n++) {
            // (xn, xn) replicated — one aligned LDS.64, broadcast across lanes
            const float2 xnv = *reinterpret_cast<const float2*>(&xd[2 * (L_ + n)]);
            const unsigned long long xn2 = pack2(xnv.x, xnv.y);

            // a2[ip] = (xn*x[n-l1], xn*x[n-l1-1])  -> lanes (l1, l1+1)
            unsigned long long a2[4];
#pragma unroll
            for (int ip = 0; ip < 4; ip++) {
                const int l1 = l1off + 32 * ip;
                const float lo = xs[L_ + n - l1];       // l1
                const float hi = xs[L_ + n - l1 - 1];   // l1+1
                a2[ip] = mul2(xn2, pack2(lo, hi));
            }

            // b2[j] = (xb, xb) replicated — aligned LDS.64 from duplicated array
            unsigned long long b2[8];
#pragma unroll
            for (int j = 0; j < 8; j++) {
                const int l2 = l2_base + tx + 16 * j;
                const float2 xv = *reinterpret_cast<const float2*>(&xd[2 * (L_ + n - l2)]);
                b2[j] = pack2(xv.x, xv.y);
            }

#pragma unroll
            for (int ip = 0; ip < 4; ip++)
#pragma unroll
                for (int j = 0; j < 8; j++)
                    fma2(acc2[ip][j], a2[ip], b2[j]);
        }
    }

    const float scale = 1.0f / (float)(T_ * L_);
    float* ob = out + (size_t)b * L_ * L_;
#pragma unroll
    for (int ip = 0; ip < 4; ip++) {
        const int l1 = l1off + 32 * ip;
#pragma unroll
        for (int j = 0; j < 8; j++) {
            const int l2 = l2_base + tx + 16 * j;
            float lo, hi;
            unpack2(acc2[ip][j], lo, hi);
            ob[l1 * L_ + l2]       = lo * scale;   // l1
            ob[(l1 + 1) * L_ + l2] = hi * scale;   // l1+1
        }
    }
}

extern "C" void kernel_launch(void* const* d_in, const int* in_sizes, int n_in,
                              void* d_out, int out_size)
{
    const float* tgt = (const float*)d_in[0];
    float* out = (float*)d_out;

    dim3 grid(4, B_);
    bispectrum_kernel<<<grid, 256>>>(tgt, out);

    // Reference returns (source, target): echo target after source if the
    // output buffer holds both.
    const long long src_elems = (long long)B_ * L_ * L_;        // 2,097,152
    const long long tgt_elems = (long long)B_ * T_ * L_;        // 65,536
    if ((long long)out_size >= src_elems + tgt_elems) {
        cudaMemcpyAsync(out + src_elems, tgt, sizeof(float) * tgt_elems,
                        cudaMemcpyDeviceToDevice);
    }
}

// round 7
// speedup vs baseline: 4.7365x; 4.7365x over previous
#include <cuda_runtime.h>
#include <cuda_fp16.h>
#include <cstdint>

// Problem constants (target: [B, T, L] float32)
constexpr int B_ = 32;
constexpr int T_ = 8;
constexpr int L_ = 256;

// GEMM formulation per (b, t):
//   S[l, k] = x[k - l]  (0 for k < l)      -- Toeplitz, fp16 in smem
//   A[m, k] = x[k] * S[m, k]               -- built in registers from S + xh
//   TM[m, l2] = sum_k A[m,k] * S[l2,k]     -- mma.sync m16n8k16 f16 -> f32
// Accumulated over t in registers; scaled by 1/(T*L) at the end.
//
// Grid: 128 CTAs = 32 batches x 4 n-strips (m = all 256, n = 64-wide strip).
// Block: 256 threads (8 warps); warp w owns rows [32w, 32w+32) x 64 n.
// tcgen05 is unavailable here (harness lowers PTX at compute_103 family
// target, which rejects arch-specific instructions) -> mma.sync only.

constexpr int SROW = 528;               // S row stride bytes (264 halfs): bank = lane
// smem layout (bytes)
constexpr int SM_XS  = 0;               // float xs[512]:  [0..255]=0 pad, [256..511]=x
constexpr int SM_XSS = 2048;            // float xss[512]: xss[i] = xs[i+1]
constexpr int SM_XH  = 4096;            // __half xh[512]: fp16 copy of xs
constexpr int SM_S   = 5120;            // fp16 S tile: 256 rows x SROW bytes
constexpr int SM_TOTAL = SM_S + 256 * SROW;   // 140288

__device__ __forceinline__ uint32_t hmul2(uint32_t a, uint32_t b) {
    uint32_t d;
    asm("mul.rn.f16x2 %0, %1, %2;" : "=r"(d) : "r"(a), "r"(b));
    return d;
}
__device__ __forceinline__ void mma16816(float* d, const uint32_t* a,
                                         uint32_t b0, uint32_t b1) {
    asm volatile(
        "mma.sync.aligned.m16n8k16.row.col.f32.f16.f16.f32 "
        "{%0,%1,%2,%3}, {%4,%5,%6,%7}, {%8,%9}, {%0,%1,%2,%3};"
        : "+f"(d[0]), "+f"(d[1]), "+f"(d[2]), "+f"(d[3])
        : "r"(a[0]), "r"(a[1]), "r"(a[2]), "r"(a[3]), "r"(b0), "r"(b1));
}

__global__ __launch_bounds__(256, 1)
void bispectrum_mma_kernel(const float* __restrict__ tgt, float* __restrict__ out)
{
    extern __shared__ char sm[];
    float*  xs  = (float*)(sm + SM_XS);
    float*  xss = (float*)(sm + SM_XSS);
    __half* xh  = (__half*)(sm + SM_XH);
    char*   S   = sm + SM_S;

    const int tid  = threadIdx.x;
    const int w    = tid >> 5;
    const int lane = tid & 31;
    const int g    = lane >> 2;     // 0..7
    const int q    = lane & 3;      // 0..3

    const int b  = blockIdx.x >> 2;
    const int n0 = (blockIdx.x & 3) * 64;

    // one-time zero init of pads
    xs[tid < 256 ? tid : 256]  = 0.0f;     // xs[0..255] = 0
    if (tid < 256) { xss[tid] = 0.0f; xh[tid] = __float2half_rn(0.0f); }

    float acc[2][8][4];
#pragma unroll
    for (int mb = 0; mb < 2; mb++)
#pragma unroll
        for (int nt = 0; nt < 8; nt++)
#pragma unroll
            for (int c = 0; c < 4; c++) acc[mb][nt][c] = 0.0f;

    // fragment base pointers (constant across t)
    const char* aP = S + (w * 32 + g) * SROW + q * 4;        // A rows = warp's m
    const char* bP = S + (n0 + g) * SROW + q * 4;            // B rows = strip's n
    const uint32_t* xkP = (const uint32_t*)xh + 128 + q;     // xh2[128 + kt*8 + q]

    for (int t = 0; t < T_; t++) {
        __syncthreads();                 // everyone done reading S of t-1
        const float v = tgt[(b * T_ + t) * L_ + tid];
        xs[256 + tid]  = v;
        xss[255 + tid] = v;              // xss[i] = xs[i+1]
        xh[256 + tid]  = __float2half_rn(v);
        __syncthreads();

        // ---- build S tile (fp16, Toeplitz): warp w -> rows [32w, 32w+32) ----
        for (int i = 0; i < 32; i++) {
            const int r = w * 32 + i;
            // S[r][2k2 .. 2k2+1] = (x[2k2-r], x[2k2+1-r]); aligned float2 via
            // xs (even r) or the shifted copy xss (odd r).
            const float2* src = (r & 1)
                ? (const float2*)(xss + (L_ - r - 1))
                : (const float2*)(xs  + (L_ - r));
            uint32_t* dst = (uint32_t*)(S + r * SROW);
#pragma unroll
            for (int j = 0; j < 4; j++) {
                const int k2 = lane + 32 * j;
                const float2 f = src[k2];
                const __half2 h = __float22half2_rn(f);
                dst[k2] = *(const uint32_t*)&h;
            }
        }
        __syncthreads();

        // ---- MMA phase: K = 256 in 16 steps of k16 ----
#pragma unroll 4
        for (int kt = 0; kt < 16; kt++) {
            const uint32_t xk0 = xkP[kt * 8];        // (x[k], x[k+1]) halves
            const uint32_t xk1 = xkP[kt * 8 + 4];    // (x[k+8], x[k+9])

            uint32_t A[2][4];
#pragma unroll
            for (int mb = 0; mb < 2; mb++) {
                const char* ab = aP + mb * (16 * SROW) + kt * 32;
                const uint32_t s0 = *(const uint32_t*)(ab);
                const uint32_t s1 = *(const uint32_t*)(ab + 8 * SROW);
                const uint32_t s2 = *(const uint32_t*)(ab + 16);
                const uint32_t s3 = *(const uint32_t*)(ab + 8 * SROW + 16);
                A[mb][0] = hmul2(s0, xk0);
                A[mb][1] = hmul2(s1, xk0);
                A[mb][2] = hmul2(s2, xk1);
                A[mb][3] = hmul2(s3, xk1);
            }
#pragma unroll
            for (int nt = 0; nt < 8; nt++) {
                const char* bb = bP + nt * (8 * SROW) + kt * 32;
                const uint32_t b0 = *(const uint32_t*)(bb);
                const uint32_t b1 = *(const uint32_t*)(bb + 16);
                mma16816(acc[0][nt], A[0], b0, b1);
                mma16816(acc[1][nt], A[1], b0, b1);
            }
        }
    }

    // ---- epilogue ----
    const float scale = 1.0f / (float)(T_ * L_);
    float* ob = out + (size_t)b * L_ * L_;
    const int m_base = w * 32 + g;
    const int n_base = n0 + q * 2;
#pragma unroll
    for (int mb = 0; mb < 2; mb++) {
#pragma unroll
        for (int nt = 0; nt < 8; nt++) {
            const int m = m_base + mb * 16;
            const int n = n_base + nt * 8;
            float2 v0 = { acc[mb][nt][0] * scale, acc[mb][nt][1] * scale };
            float2 v1 = { acc[mb][nt][2] * scale, acc[mb][nt][3] * scale };
            *(float2*)&ob[(size_t)m * L_ + n]       = v0;
            *(float2*)&ob[(size_t)(m + 8) * L_ + n] = v1;
        }
    }
}

extern "C" void kernel_launch(void* const* d_in, const int* in_sizes, int n_in,
                              void* d_out, int out_size)
{
    const float* tgt = (const float*)d_in[0];
    float* out = (float*)d_out;

    cudaFuncSetAttribute(bispectrum_mma_kernel,
                         cudaFuncAttributeMaxDynamicSharedMemorySize, SM_TOTAL);

    bispectrum_mma_kernel<<<128, 256, SM_TOTAL>>>(tgt, out);

    // Reference returns (source, target): echo target after source if the
    // output buffer holds both.
    const long long src_elems = (long long)B_ * L_ * L_;        // 2,097,152
    const long long tgt_elems = (long long)B_ * T_ * L_;        // 65,536
    if ((long long)out_size >= src_elems + tgt_elems) {
        cudaMemcpyAsync(out + src_elems, tgt, sizeof(float) * tgt_elems,
                        cudaMemcpyDeviceToDevice);
    }
}

// round 8
// speedup vs baseline: 4.9425x; 1.0435x over previous
#include <cuda_runtime.h>
#include <cuda_fp16.h>
#include <cstdint>

// Problem constants (target: [B, T, L] float32)
constexpr int B_ = 32;
constexpr int T_ = 8;
constexpr int L_ = 256;

// GEMM formulation per (b, t):
//   S[l, k] = x[k - l]  (0 for k < l)     -- Toeplitz, fp16 in smem
//   A[m, k] = x[k] * S[m, k]              -- built in registers (hmul2)
//   TM[m, l2] = sum_k A[m,k] * S[l2,k]    -- mma.sync m16n8k16 f16 -> f32
//
// Grid: 128 CTAs = 32 batches x 4 n-strips (m = all 256, n = 64-wide strip).
// Block: 512 threads (16 warps, occ 25%); warp w owns m-rows [16w, 16w+16).
// Fragments loaded with ldmatrix.x4 (5 per k16 step instead of 24 LDS.32);
// Toeplitz build uses 4 shifted fp32 copies of the padded signal so every
// load is an aligned LDS.128 and every store a conflict-free STS.64.

constexpr int SROW = 528;               // S row stride bytes: row-start bank = 4r mod 32
// smem layout (bytes)
constexpr int SM_XSH = 0;               // float xsh[4][512]; xsh[s][i] = padded_x[i+s]
constexpr int SM_XH  = 8192;            // __half xh[512] (padded fp16 signal)
constexpr int SM_S   = 9216;            // fp16 S tile: 256 rows x SROW bytes
constexpr int SM_TOTAL = SM_S + 256 * SROW;   // 144384

__device__ __forceinline__ uint32_t smem_u32(const void* p) {
    uint32_t a;
    asm("{ .reg .u64 t; cvta.to.shared.u64 t, %1; cvt.u32.u64 %0, t; }" : "=r"(a) : "l"(p));
    return a;
}
__device__ __forceinline__ uint32_t hmul2(uint32_t a, uint32_t b) {
    uint32_t d;
    asm("mul.rn.f16x2 %0, %1, %2;" : "=r"(d) : "r"(a), "r"(b));
    return d;
}
__device__ __forceinline__ void ldsm4(uint32_t& r0, uint32_t& r1, uint32_t& r2,
                                      uint32_t& r3, uint32_t addr) {
    asm volatile("ldmatrix.sync.aligned.m8n8.x4.shared.b16 {%0,%1,%2,%3}, [%4];"
                 : "=r"(r0), "=r"(r1), "=r"(r2), "=r"(r3) : "r"(addr));
}
__device__ __forceinline__ void mma16816(float* d, const uint32_t* a,
                                         uint32_t b0, uint32_t b1) {
    asm volatile(
        "mma.sync.aligned.m16n8k16.row.col.f32.f16.f16.f32 "
        "{%0,%1,%2,%3}, {%4,%5,%6,%7}, {%8,%9}, {%0,%1,%2,%3};"
        : "+f"(d[0]), "+f"(d[1]), "+f"(d[2]), "+f"(d[3])
        : "r"(a[0]), "r"(a[1]), "r"(a[2]), "r"(a[3]), "r"(b0), "r"(b1));
}

__global__ __launch_bounds__(512, 1)
void bispectrum_mma_kernel(const float* __restrict__ tgt, float* __restrict__ out)
{
    extern __shared__ char sm[];
    float*  xsh = (float*)(sm + SM_XSH);
    __half* xh  = (__half*)(sm + SM_XH);
    char*   S   = sm + SM_S;

    const int tid  = threadIdx.x;
    const int w    = tid >> 5;
    const int lane = tid & 31;
    const int g    = lane >> 2;     // 0..7
    const int q    = lane & 3;      // 0..3

    const int b  = blockIdx.x >> 2;
    const int n0 = (blockIdx.x & 3) * 64;

    // one-time zero init of static pad regions
    if (tid < 256) {
#pragma unroll
        for (int s = 0; s < 4; s++) xsh[s * 512 + tid] = 0.0f;
        xh[tid] = __float2half_rn(0.0f);
    }

    float acc[8][4];
#pragma unroll
    for (int nt = 0; nt < 8; nt++)
#pragma unroll
        for (int c = 0; c < 4; c++) acc[nt][c] = 0.0f;

    // ---- per-lane ldmatrix base addresses (constant across t / kt) ----
    const uint32_t sS = smem_u32(S);
    // A x4: m0 = rows g @+0, m1 = rows g+8 @+0, m2 = rows g @+16, m3 = rows g+8 @+16
    const uint32_t aAddr = sS + (uint32_t)(16 * w + (lane & 15)) * SROW
                              + ((lane & 16) ? 16u : 0u);
    // B x4 (pair p -> nt=2p,2p+1): m0 = rows nt*8 @+0, m1 = @+16, m2 = rows +8 @+0, m3 = @+16
    uint32_t bAddr[4];
    {
        const int rb = n0 + (lane & 7) + ((lane & 16) ? 8 : 0);
        const uint32_t ob = (lane & 8) ? 16u : 0u;
#pragma unroll
        for (int p = 0; p < 4; p++) bAddr[p] = sS + (uint32_t)(rb + 16 * p) * SROW + ob;
    }
    // scalar k broadcast: xk0 = (x[k0+2q], x[k0+2q+1]) as packed half2
    const uint32_t* xku = (const uint32_t*)xh + 128 + q;

    for (int t = 0; t < T_; t++) {
        __syncthreads();                   // previous MMA phase done reading S / xh
        if (tid < 256) {
            const float v = tgt[(b * T_ + t) * L_ + tid];
#pragma unroll
            for (int s = 0; s < 4; s++) xsh[s * 512 + 256 + tid - s] = v;
            xh[256 + tid] = __float2half_rn(v);
        }
        __syncthreads();

        // ---- build S tile: warp w -> rows [16w, 16w+16) ----
        // S[r][k] = padded_x[256 - r + k]; use shift copy s = (-r) mod 4 so the
        // base index is a multiple of 4 -> aligned float4 loads. r = 16w + i and
        // 16w % 4 == 0, so s depends only on i (compile-time in unrolled loop).
#pragma unroll
        for (int i = 0; i < 16; i++) {
            const int r = 16 * w + i;
            constexpr int smask[4] = { 0, 3, 2, 1 };
            const int s = smask[i & 3];
            const float4* src = (const float4*)(xsh + s * 512 + (256 - r - s));
            uint2* dst = (uint2*)(S + r * SROW);
#pragma unroll
            for (int h = 0; h < 2; h++) {
                const int c = lane + 32 * h;           // float4 chunk (0..63)
                const float4 f = src[c];
                const __half2 lo = __floats2half2_rn(f.x, f.y);
                const __half2 hi = __floats2half2_rn(f.z, f.w);
                uint2 u;
                u.x = *(const uint32_t*)&lo;
                u.y = *(const uint32_t*)&hi;
                dst[c] = u;
            }
        }
        __syncthreads();

        // ---- MMA phase: K = 256 in 16 steps of k16 ----
#pragma unroll 4
        for (int kt = 0; kt < 16; kt++) {
            const uint32_t xk0 = xku[kt * 8];          // (x[k], x[k+1])
            const uint32_t xk1 = xku[kt * 8 + 4];      // (x[k+8], x[k+9])

            uint32_t a0, a1, a2, a3;
            ldsm4(a0, a1, a2, a3, aAddr + kt * 32);
            uint32_t Af[4];
            Af[0] = hmul2(a0, xk0);
            Af[1] = hmul2(a1, xk0);
            Af[2] = hmul2(a2, xk1);
            Af[3] = hmul2(a3, xk1);

#pragma unroll
            for (int p = 0; p < 4; p++) {
                uint32_t b0, b1, b2, b3;
                ldsm4(b0, b1, b2, b3, bAddr[p] + kt * 32);
                mma16816(acc[2 * p],     Af, b0, b1);
                mma16816(acc[2 * p + 1], Af, b2, b3);
            }
        }
    }

    // ---- epilogue ----
    const float scale = 1.0f / (float)(T_ * L_);
    float* ob = out + (size_t)b * L_ * L_;
    const int m = 16 * w + g;
    const int n_base = n0 + q * 2;
#pragma unroll
    for (int nt = 0; nt < 8; nt++) {
        const int n = n_base + nt * 8;
        float2 v0 = { acc[nt][0] * scale, acc[nt][1] * scale };
        float2 v1 = { acc[nt][2] * scale, acc[nt][3] * scale };
        *(float2*)&ob[(size_t)m * L_ + n]       = v0;
        *(float2*)&ob[(size_t)(m + 8) * L_ + n] = v1;
    }
}

extern "C" void kernel_launch(void* const* d_in, const int* in_sizes, int n_in,
                              void* d_out, int out_size)
{
    const float* tgt = (const float*)d_in[0];
    float* out = (float*)d_out;

    cudaFuncSetAttribute(bispectrum_mma_kernel,
                         cudaFuncAttributeMaxDynamicSharedMemorySize, SM_TOTAL);

    bispectrum_mma_kernel<<<128, 512, SM_TOTAL>>>(tgt, out);

    // Reference returns (source, target): echo target after source if the
    // output buffer holds both.
    const long long src_elems = (long long)B_ * L_ * L_;        // 2,097,152
    const long long tgt_elems = (long long)B_ * T_ * L_;        // 65,536
    if ((long long)out_size >= src_elems + tgt_elems) {
        cudaMemcpyAsync(out + src_elems, tgt, sizeof(float) * tgt_elems,
                        cudaMemcpyDeviceToDevice);
    }
}

// round 9
// speedup vs baseline: 7.8108x; 1.5803x over previous
#include <cuda_runtime.h>
#include <cuda_fp16.h>
#include <cstdint>

// Problem constants (target: [B, T, L] float32)
constexpr int B_ = 32;
constexpr int T_ = 8;
constexpr int L_ = 256;

// GEMM formulation per (b, t):
//   S[l, k] = x[k - l]  (0 for k < l)     -- Toeplitz: NEVER materialized.
//   A[m, k] = x[k] * S[m, k]              -- built in registers (hmul2)
//   TM[m, l2] = sum_k A[m,k] * S[l2,k]    -- mma.sync m16n8k16 f16 -> f32
//
// Because S is Toeplitz, every ldmatrix row (16B) is a shifted window of the
// signal. We keep 8 SHIFT-COPIES of the padded fp16 signal in smem
// (copy_s[i] = x_pad[i+s]) so each row address is 16B-aligned, and place the
// copies at bases E_s = 1168*s (+112 for s=0) so that within every 8-row
// ldmatrix phase the bank groups form a perfect permutation -> conflict-free.
// This removes the entire per-t S-tile build (the old crossbar hog).
//
// Grid: 128 CTAs = 32 batches x 4 n-strips. Block: 512 threads, 16 warps as
// 8(m) x 2(n); warp tile 32x32 (4 ldsm.x4 + 8 MMA per k16 step).

__device__ __forceinline__ uint32_t smem_u32(const void* p) {
    uint32_t a;
    asm("{ .reg .u64 t; cvta.to.shared.u64 t, %1; cvt.u32.u64 %0, t; }" : "=r"(a) : "l"(p));
    return a;
}
__device__ __forceinline__ uint32_t hmul2(uint32_t a, uint32_t b) {
    uint32_t d;
    asm("mul.rn.f16x2 %0, %1, %2;" : "=r"(d) : "r"(a), "r"(b));
    return d;
}
__device__ __forceinline__ void ldsm4(uint32_t& r0, uint32_t& r1, uint32_t& r2,
                                      uint32_t& r3, uint32_t addr) {
    asm volatile("ldmatrix.sync.aligned.m8n8.x4.shared.b16 {%0,%1,%2,%3}, [%4];"
                 : "=r"(r0), "=r"(r1), "=r"(r2), "=r"(r3) : "r"(addr));
}
__device__ __forceinline__ void mma16816(float* d, const uint32_t* a,
                                         uint32_t b0, uint32_t b1) {
    asm volatile(
        "mma.sync.aligned.m16n8k16.row.col.f32.f16.f16.f32 "
        "{%0,%1,%2,%3}, {%4,%5,%6,%7}, {%8,%9}, {%0,%1,%2,%3};"
        : "+f"(d[0]), "+f"(d[1]), "+f"(d[2]), "+f"(d[3])
        : "r"(a[0]), "r"(a[1]), "r"(a[2]), "r"(a[3]), "r"(b0), "r"(b1));
}

// copy base (bytes): E_s = 1168*s + (s==0 ? 112 : 0)
//   = 1152*s + 16*e_s with e_0=7, e_s=s  -> phase bank groups = permutation
__device__ __forceinline__ uint32_t copy_base(int s) {
    return 1168u * s + (s == 0 ? 112u : 0u);
}

constexpr int SMEM_BYTES = 9216;   // E_7 + 1024 = 9200, padded

__global__ __launch_bounds__(512, 1)
void bispectrum_mma_kernel(const float* __restrict__ tgt, float* __restrict__ out)
{
    __shared__ __align__(16) unsigned char smb[SMEM_BYTES];
    const uint32_t sB = smem_u32(smb);

    const int tid  = threadIdx.x;
    const int w    = tid >> 5;
    const int lane = tid & 31;
    const int g    = lane >> 2;     // 0..7
    const int q    = lane & 3;      // 0..3

    const int b  = blockIdx.x >> 2;
    const int n0 = (blockIdx.x & 3) * 64;

    const int mBase = 32 * (w >> 1);          // warp m rows [mBase, mBase+32)
    const int nBase = n0 + 32 * (w & 1);      // warp n rows [nBase, nBase+32)

    // zero all copies once (left pads stay zero forever)
    for (int i = tid; i < SMEM_BYTES / 4; i += 512)
        *(uint32_t*)(smb + 4 * i) = 0u;

    float acc[2][4][4];
#pragma unroll
    for (int mt = 0; mt < 2; mt++)
#pragma unroll
        for (int j = 0; j < 4; j++)
#pragma unroll
            for (int c = 0; c < 4; c++) acc[mt][j][c] = 0.0f;

    // ---- per-lane ldmatrix base addresses (constant across t, += 32B per kt)
    // row u, col-shift cs (halfs): addr = E(s) + (256 + cs - u - s)*2, s=(-u)&7
    uint32_t aBase[2], bBase[2];
#pragma unroll
    for (int mt = 0; mt < 2; mt++) {
        const int u  = mBase + mt * 16 + (lane & 15);
        const int cs = (lane & 16) ? 8 : 0;
        const int s  = (-u) & 7;
        aBase[mt] = sB + copy_base(s) + (uint32_t)(256 + cs - u - s) * 2;
    }
#pragma unroll
    for (int nb = 0; nb < 2; nb++) {
        const int u  = nBase + nb * 16 + (lane & 7) + ((lane & 16) ? 8 : 0);
        const int cs = (lane & 8) ? 8 : 0;
        const int s  = (-u) & 7;
        bBase[nb] = sB + copy_base(s) + (uint32_t)(256 + cs - u - s) * 2;
    }
    // scalar k broadcast from copy 0 (plain padded signal): half2 at 256+16kt+2q
    const uint32_t xkA = sB + 112u + 512u + 4u * q;   // += 32 per kt

    for (int t = 0; t < T_; t++) {
        __syncthreads();                   // previous MMA phase done reading copies
        if (tid < 256) {
            const __half h = __float2half_rn(tgt[(b * T_ + t) * L_ + tid]);
#pragma unroll
            for (int s = 0; s < 8; s++) {
                // copy_s[256 + tid - s] = x[tid]
                *(__half*)(smb + copy_base(s) + (uint32_t)(256 + tid - s) * 2) = h;
            }
        }
        __syncthreads();

        // ---- MMA phase: K = 256 in 16 steps of k16, no tile build needed ----
#pragma unroll 4
        for (int kt = 0; kt < 16; kt++) {
            const uint32_t koff = (uint32_t)kt * 32u;
            uint32_t xk0, xk1;
            asm volatile("ld.shared.b32 %0, [%1];" : "=r"(xk0) : "r"(xkA + koff));
            asm volatile("ld.shared.b32 %0, [%1];" : "=r"(xk1) : "r"(xkA + koff + 16));

            uint32_t Af[2][4];
#pragma unroll
            for (int mt = 0; mt < 2; mt++) {
                uint32_t a0, a1, a2, a3;
                ldsm4(a0, a1, a2, a3, aBase[mt] + koff);
                Af[mt][0] = hmul2(a0, xk0);
                Af[mt][1] = hmul2(a1, xk0);
                Af[mt][2] = hmul2(a2, xk1);
                Af[mt][3] = hmul2(a3, xk1);
            }
#pragma unroll
            for (int nb = 0; nb < 2; nb++) {
                uint32_t b0, b1, b2, b3;
                ldsm4(b0, b1, b2, b3, bBase[nb] + koff);
#pragma unroll
                for (int mt = 0; mt < 2; mt++) {
                    mma16816(acc[mt][2 * nb],     Af[mt], b0, b1);
                    mma16816(acc[mt][2 * nb + 1], Af[mt], b2, b3);
                }
            }
        }
    }

    // ---- epilogue ----
    const float scale = 1.0f / (float)(T_ * L_);
    float* ob = out + (size_t)b * L_ * L_;
#pragma unroll
    for (int mt = 0; mt < 2; mt++) {
        const int m = mBase + mt * 16 + g;
#pragma unroll
        for (int j = 0; j < 4; j++) {
            const int n = nBase + 8 * j + 2 * q;
            float2 v0 = { acc[mt][j][0] * scale, acc[mt][j][1] * scale };
            float2 v1 = { acc[mt][j][2] * scale, acc[mt][j][3] * scale };
            *(float2*)&ob[(size_t)m * L_ + n]       = v0;
            *(float2*)&ob[(size_t)(m + 8) * L_ + n] = v1;
        }
    }
}

extern "C" void kernel_launch(void* const* d_in, const int* in_sizes, int n_in,
                              void* d_out, int out_size)
{
    const float* tgt = (const float*)d_in[0];
    float* out = (float*)d_out;

    bispectrum_mma_kernel<<<128, 512>>>(tgt, out);

    // Reference returns (source, target): echo target after source if the
    // output buffer holds both.
    const long long src_elems = (long long)B_ * L_ * L_;        // 2,097,152
    const long long tgt_elems = (long long)B_ * T_ * L_;        // 65,536
    if ((long long)out_size >= src_elems + tgt_elems) {
        cudaMemcpyAsync(out + src_elems, tgt, sizeof(float) * tgt_elems,
                        cudaMemcpyDeviceToDevice);
    }
}

// round 10
// speedup vs baseline: 8.0315x; 1.0283x over previous
#include <cuda_runtime.h>
#include <cuda_fp16.h>
#include <cstdint>

// Problem constants (target: [B, T, L] float32)
constexpr int B_ = 32;
constexpr int T_ = 8;
constexpr int L_ = 256;

// GEMM formulation per (b, t):
//   S[l, k] = x[k - l]  (0 for k < l)     -- Toeplitz: never materialized.
//   A[m, k] = x[k] * S[m, k]              -- built in registers (hmul2)
//   TM[m, l2] = sum_k A[m,k] * S[l2,k]    -- mma.sync m16n8k16 f16 -> f32
//
// Toeplitz rows are shifted 16B windows of the signal: ldmatrix reads directly
// from 8 shift-copies of the padded fp16 signal (copy_s[i] = x_pad[i+s]),
// placed at bases E_s = 1168*s (+112 for s=0) so every 8-row ldmatrix phase
// hits a perfect bank-group permutation (conflict-free, verified R9).
//
// R10: occupancy doubling. Grid 256 CTAs = 32 b x 8 n-strips (32 wide),
// 512 threads, __launch_bounds__(512,2) -> 2 CTAs/SM, 32 warps/SM.
// 16 warps = 8 m-tiles (32x32) x 2 t-groups (t 0-3 / 4-7, own copy set each).
// t-split reduced INTRA-CTA via a smem merge buffer (no global atomics).

__device__ __forceinline__ uint32_t smem_u32(const void* p) {
    uint32_t a;
    asm("{ .reg .u64 t; cvta.to.shared.u64 t, %1; cvt.u32.u64 %0, t; }" : "=r"(a) : "l"(p));
    return a;
}
__device__ __forceinline__ uint32_t hmul2(uint32_t a, uint32_t b) {
    uint32_t d;
    asm("mul.rn.f16x2 %0, %1, %2;" : "=r"(d) : "r"(a), "r"(b));
    return d;
}
__device__ __forceinline__ void ldsm4(uint32_t& r0, uint32_t& r1, uint32_t& r2,
                                      uint32_t& r3, uint32_t addr) {
    asm volatile("ldmatrix.sync.aligned.m8n8.x4.shared.b16 {%0,%1,%2,%3}, [%4];"
                 : "=r"(r0), "=r"(r1), "=r"(r2), "=r"(r3) : "r"(addr));
}
__device__ __forceinline__ void mma16816(float* d, const uint32_t* a,
                                         uint32_t b0, uint32_t b1) {
    asm volatile(
        "mma.sync.aligned.m16n8k16.row.col.f32.f16.f16.f32 "
        "{%0,%1,%2,%3}, {%4,%5,%6,%7}, {%8,%9}, {%0,%1,%2,%3};"
        : "+f"(d[0]), "+f"(d[1]), "+f"(d[2]), "+f"(d[3])
        : "r"(a[0]), "r"(a[1]), "r"(a[2]), "r"(a[3]), "r"(b0), "r"(b1));
}

// copy base within a copy set (bytes): E_s = 1168*s + (s==0 ? 112 : 0)
__device__ __forceinline__ uint32_t copy_base(int s) {
    return 1168u * s + (s == 0 ? 112u : 0u);
}

constexpr int COPYSET  = 9216;                 // bytes per t-group copy set
constexpr int SM_MERGE = 2 * COPYSET;          // 18432
constexpr int SM_TOTAL = SM_MERGE + 8 * 1024 * 4;   // + 32KB merge = 51200

__global__ __launch_bounds__(512, 2)
void bispectrum_mma_kernel(const float* __restrict__ tgt, float* __restrict__ out)
{
    extern __shared__ __align__(16) unsigned char smb[];
    const uint32_t sB = smem_u32(smb);
    float* mg = (float*)(smb + SM_MERGE);

    const int tid  = threadIdx.x;
    const int w    = tid >> 5;
    const int lane = tid & 31;
    const int g    = lane >> 2;     // 0..7
    const int q    = lane & 3;      // 0..3

    const int b  = blockIdx.x >> 3;
    const int n0 = (blockIdx.x & 7) * 32;

    const int tile = w & 7;                    // m-tile index
    const int grp  = w >> 3;                   // t-group (0: t 0-3, 1: t 4-7)
    const int mBase = 32 * tile;
    const uint32_t cOff = (uint32_t)grp * COPYSET;

    // zero both copy sets once (left pads stay zero forever)
    for (int i = tid; i < 2 * COPYSET / 4; i += 512)
        *(uint32_t*)(smb + 4 * i) = 0u;

    float acc[2][4][4];
#pragma unroll
    for (int mt = 0; mt < 2; mt++)
#pragma unroll
        for (int j = 0; j < 4; j++)
#pragma unroll
            for (int c = 0; c < 4; c++) acc[mt][j][c] = 0.0f;

    // ---- per-lane ldmatrix base addresses (constant across t, += 32B per kt)
    // row u, col-shift cs (halfs): addr = E(s) + (256 + cs - u - s)*2, s=(-u)&7
    uint32_t aBase[2], bBase[2];
#pragma unroll
    for (int mt = 0; mt < 2; mt++) {
        const int u  = mBase + mt * 16 + (lane & 15);
        const int cs = (lane & 16) ? 8 : 0;
        const int s  = (-u) & 7;
        aBase[mt] = sB + cOff + copy_base(s) + (uint32_t)(256 + cs - u - s) * 2;
    }
#pragma unroll
    for (int nb = 0; nb < 2; nb++) {
        const int u  = n0 + nb * 16 + (lane & 7) + ((lane & 16) ? 8 : 0);
        const int cs = (lane & 8) ? 8 : 0;
        const int s  = (-u) & 7;
        bBase[nb] = sB + cOff + copy_base(s) + (uint32_t)(256 + cs - u - s) * 2;
    }
    // scalar k broadcast from copy 0 of this group's set: half2 at 256+16kt+2q
    const uint32_t xkA = sB + cOff + 112u + 512u + 4u * q;   // += 32 per kt

    // signal writer role: wg's copy set, element idx
    const int wg  = tid >> 8;        // 0/1
    const int idx = tid & 255;

    for (int tt = 0; tt < 4; tt++) {
        __syncthreads();                   // previous MMA phase done reading copies
        {
            const __half h = __float2half_rn(
                tgt[(b * T_ + tt + 4 * wg) * L_ + idx]);
#pragma unroll
            for (int s = 0; s < 8; s++)
                *(__half*)(smb + wg * COPYSET + copy_base(s) +
                           (uint32_t)(256 + idx - s) * 2) = h;
        }
        __syncthreads();

        // ---- MMA phase: K = 256 in 16 steps of k16 ----
#pragma unroll 4
        for (int kt = 0; kt < 16; kt++) {
            const uint32_t koff = (uint32_t)kt * 32u;
            uint32_t xk0, xk1;
            asm volatile("ld.shared.b32 %0, [%1];" : "=r"(xk0) : "r"(xkA + koff));
            asm volatile("ld.shared.b32 %0, [%1];" : "=r"(xk1) : "r"(xkA + koff + 16));

            uint32_t Af[2][4];
#pragma unroll
            for (int mt = 0; mt < 2; mt++) {
                uint32_t a0, a1, a2, a3;
                ldsm4(a0, a1, a2, a3, aBase[mt] + koff);
                Af[mt][0] = hmul2(a0, xk0);
                Af[mt][1] = hmul2(a1, xk0);
                Af[mt][2] = hmul2(a2, xk1);
                Af[mt][3] = hmul2(a3, xk1);
            }
#pragma unroll
            for (int nb = 0; nb < 2; nb++) {
                uint32_t b0, b1, b2, b3;
                ldsm4(b0, b1, b2, b3, bBase[nb] + koff);
#pragma unroll
                for (int mt = 0; mt < 2; mt++) {
                    mma16816(acc[mt][2 * nb],     Af[mt], b0, b1);
                    mma16816(acc[mt][2 * nb + 1], Af[mt], b2, b3);
                }
            }
        }
    }

    // ---- merge t-groups (intra-CTA) + epilogue ----
    __syncthreads();
    if (grp == 1) {
        float* mt_ = mg + tile * 1024 + lane;   // [i*32 + lane] : conflict-free
#pragma unroll
        for (int mt = 0; mt < 2; mt++)
#pragma unroll
            for (int j = 0; j < 4; j++)
#pragma unroll
                for (int c = 0; c < 4; c++)
                    mt_[(mt * 16 + j * 4 + c) * 32] = acc[mt][j][c];
    }
    __syncthreads();
    if (grp == 0) {
        const float scale = 1.0f / (float)(T_ * L_);
        const float* mt_ = mg + tile * 1024 + lane;
        float* ob = out + (size_t)b * L_ * L_;
#pragma unroll
        for (int mt = 0; mt < 2; mt++) {
            const int m = mBase + mt * 16 + g;
#pragma unroll
            for (int j = 0; j < 4; j++) {
                const int n = n0 + 8 * j + 2 * q;
                const int i0 = (mt * 16 + j * 4) * 32;
                float2 v0, v1;
                v0.x = (acc[mt][j][0] + mt_[i0])      * scale;
                v0.y = (acc[mt][j][1] + mt_[i0 + 32]) * scale;
                v1.x = (acc[mt][j][2] + mt_[i0 + 64]) * scale;
                v1.y = (acc[mt][j][3] + mt_[i0 + 96]) * scale;
                *(float2*)&ob[(size_t)m * L_ + n]       = v0;
                *(float2*)&ob[(size_t)(m + 8) * L_ + n] = v1;
            }
        }
    }
}

extern "C" void kernel_launch(void* const* d_in, const int* in_sizes, int n_in,
                              void* d_out, int out_size)
{
    const float* tgt = (const float*)d_in[0];
    float* out = (float*)d_out;

    cudaFuncSetAttribute(bispectrum_mma_kernel,
                         cudaFuncAttributeMaxDynamicSharedMemorySize, SM_TOTAL);

    bispectrum_mma_kernel<<<256, 512, SM_TOTAL>>>(tgt, out);

    // Reference returns (source, target): echo target after source if the
    // output buffer holds both.
    const long long src_elems = (long long)B_ * L_ * L_;        // 2,097,152
    const long long tgt_elems = (long long)B_ * T_ * L_;        // 65,536
    if ((long long)out_size >= src_elems + tgt_elems) {
        cudaMemcpyAsync(out + src_elems, tgt, sizeof(float) * tgt_elems,
                        cudaMemcpyDeviceToDevice);
    }
}

// round 11
// speedup vs baseline: 8.5225x; 1.0611x over previous
#include <cuda_runtime.h>
#include <cuda_fp16.h>
#include <cstdint>

// Problem constants (target: [B, T, L] float32)
constexpr int B_ = 32;
constexpr int T_ = 8;
constexpr int L_ = 256;

// GEMM formulation per (b, t):
//   S[l, k] = x[k - l]  (0 for k < l)     -- Toeplitz: never materialized.
//   A[m, k] = x[k] * S[m, k]              -- built in registers (hmul2)
//   TM[m, l2] = sum_k A[m,k] * S[l2,k]    -- mma.sync m16n8k16 f16 -> f32
//
// ldmatrix reads directly from 8 shift-copies of the padded fp16 signal
// (copy_s[i] = x_pad[i+s]) at bases E_s = 1168*s (+112 for s=0): every 8-row
// ldmatrix phase is a perfect bank-group permutation (conflict-free).
//
// R11: FAT WARPS. Warp tile 32x64 (2 m-frags x 8 n-frags): 16 MMAs per
// 6 ldsm.x4 -> 2.1 instr/MMA, 0.094 LDSM B/MAC. CTA = 256 thr, 8 warps =
// 4 m-tiles x 2 t-groups, __launch_bounds__(256,2) -> 128-reg budget,
// 2 CTAs/SM (16 warps/SM) with real per-warp ILP headroom.
// Grid 256 = 32 b x 2 m-halves x 4 n-strips(64).

__device__ __forceinline__ uint32_t smem_u32(const void* p) {
    uint32_t a;
    asm("{ .reg .u64 t; cvta.to.shared.u64 t, %1; cvt.u32.u64 %0, t; }" : "=r"(a) : "l"(p));
    return a;
}
__device__ __forceinline__ uint32_t hmul2(uint32_t a, uint32_t b) {
    uint32_t d;
    asm("mul.rn.f16x2 %0, %1, %2;" : "=r"(d) : "r"(a), "r"(b));
    return d;
}
__device__ __forceinline__ void ldsm4(uint32_t& r0, uint32_t& r1, uint32_t& r2,
                                      uint32_t& r3, uint32_t addr) {
    asm volatile("ldmatrix.sync.aligned.m8n8.x4.shared.b16 {%0,%1,%2,%3}, [%4];"
                 : "=r"(r0), "=r"(r1), "=r"(r2), "=r"(r3) : "r"(addr));
}
__device__ __forceinline__ void mma16816(float* d, const uint32_t* a,
                                         uint32_t b0, uint32_t b1) {
    asm volatile(
        "mma.sync.aligned.m16n8k16.row.col.f32.f16.f16.f32 "
        "{%0,%1,%2,%3}, {%4,%5,%6,%7}, {%8,%9}, {%0,%1,%2,%3};"
        : "+f"(d[0]), "+f"(d[1]), "+f"(d[2]), "+f"(d[3])
        : "r"(a[0]), "r"(a[1]), "r"(a[2]), "r"(a[3]), "r"(b0), "r"(b1));
}

// copy base within a copy set (bytes): E_s = 1168*s + (s==0 ? 112 : 0)
__device__ __forceinline__ uint32_t copy_base(int s) {
    return 1168u * s + (s == 0 ? 112u : 0u);
}

constexpr int COPYSET  = 9216;                    // bytes per t-group copy set
constexpr int SM_MERGE = 2 * COPYSET;             // 18432
constexpr int SM_TOTAL = SM_MERGE + 4 * 2048 * 4; // + 32KB merge = 51200

__global__ __launch_bounds__(256, 2)
void bispectrum_mma_kernel(const float* __restrict__ tgt, float* __restrict__ out)
{
    extern __shared__ __align__(16) unsigned char smb[];
    const uint32_t sB = smem_u32(smb);
    float* mg = (float*)(smb + SM_MERGE);

    const int tid  = threadIdx.x;
    const int w    = tid >> 5;
    const int lane = tid & 31;
    const int g    = lane >> 2;     // 0..7
    const int q    = lane & 3;      // 0..3

    const int b  = blockIdx.x >> 3;
    const int r_ = blockIdx.x & 7;
    const int mh = r_ >> 2;                    // m half: 0 / 1
    const int n0 = (r_ & 3) * 64;              // n strip (64 wide)

    const int tile = w & 3;                    // m-tile within half
    const int grp  = w >> 2;                   // t-group (0: t 0-3, 1: t 4-7)
    const int mBase = mh * 128 + 32 * tile;
    const uint32_t cOff = (uint32_t)grp * COPYSET;

    // zero both copy sets once (left pads stay zero forever)
    for (int i = tid; i < 2 * COPYSET / 4; i += 256)
        *(uint32_t*)(smb + 4 * i) = 0u;

    float acc[2][8][4];
#pragma unroll
    for (int mt = 0; mt < 2; mt++)
#pragma unroll
        for (int j = 0; j < 8; j++)
#pragma unroll
            for (int c = 0; c < 4; c++) acc[mt][j][c] = 0.0f;

    // ---- per-lane ldmatrix base addresses (constant across t, += 32B per kt)
    // row u, col-shift cs (halfs): addr = E(s) + (256 + cs - u - s)*2, s=(-u)&7
    uint32_t aBase[2], bBase[4];
#pragma unroll
    for (int mt = 0; mt < 2; mt++) {
        const int u  = mBase + mt * 16 + (lane & 15);
        const int cs = (lane & 16) ? 8 : 0;
        const int s  = (-u) & 7;
        aBase[mt] = sB + cOff + copy_base(s) + (uint32_t)(256 + cs - u - s) * 2;
    }
#pragma unroll
    for (int nb = 0; nb < 4; nb++) {
        const int u  = n0 + nb * 16 + (lane & 7) + ((lane & 16) ? 8 : 0);
        const int cs = (lane & 8) ? 8 : 0;
        const int s  = (-u) & 7;
        bBase[nb] = sB + cOff + copy_base(s) + (uint32_t)(256 + cs - u - s) * 2;
    }
    // scalar k broadcast from copy 0 of this group's set: half2 at 256+16kt+2q
    const uint32_t xkA = sB + cOff + 112u + 512u + 4u * q;   // += 32 per kt

    for (int tt = 0; tt < 4; tt++) {
        __syncthreads();                   // previous MMA phase done reading copies
        // every thread writes its element into BOTH t-group copy sets
#pragma unroll
        for (int wg = 0; wg < 2; wg++) {
            const __half h = __float2half_rn(
                tgt[(b * T_ + tt + 4 * wg) * L_ + tid]);
#pragma unroll
            for (int s = 0; s < 8; s++)
                *(__half*)(smb + wg * COPYSET + copy_base(s) +
                           (uint32_t)(256 + tid - s) * 2) = h;
        }
        __syncthreads();

        // ---- MMA phase: K = 256 in 16 steps of k16 ----
#pragma unroll 4
        for (int kt = 0; kt < 16; kt++) {
            const uint32_t koff = (uint32_t)kt * 32u;
            uint32_t xk0, xk1;
            asm volatile("ld.shared.b32 %0, [%1];" : "=r"(xk0) : "r"(xkA + koff));
            asm volatile("ld.shared.b32 %0, [%1];" : "=r"(xk1) : "r"(xkA + koff + 16));

            uint32_t Af[2][4];
#pragma unroll
            for (int mt = 0; mt < 2; mt++) {
                uint32_t a0, a1, a2, a3;
                ldsm4(a0, a1, a2, a3, aBase[mt] + koff);
                Af[mt][0] = hmul2(a0, xk0);
                Af[mt][1] = hmul2(a1, xk0);
                Af[mt][2] = hmul2(a2, xk1);
                Af[mt][3] = hmul2(a3, xk1);
            }
#pragma unroll
            for (int nb = 0; nb < 4; nb++) {
                uint32_t b0, b1, b2, b3;
                ldsm4(b0, b1, b2, b3, bBase[nb] + koff);
#pragma unroll
                for (int mt = 0; mt < 2; mt++) {
                    mma16816(acc[mt][2 * nb],     Af[mt], b0, b1);
                    mma16816(acc[mt][2 * nb + 1], Af[mt], b2, b3);
                }
            }
        }
    }

    // ---- merge t-groups (intra-CTA) + epilogue ----
    __syncthreads();
    if (grp == 1) {
        float* mt_ = mg + tile * 2048 + lane;   // stride 32: conflict-free
#pragma unroll
        for (int mt = 0; mt < 2; mt++)
#pragma unroll
            for (int j = 0; j < 8; j++)
#pragma unroll
                for (int c = 0; c < 4; c++)
                    mt_[((mt * 8 + j) * 4 + c) * 32] = acc[mt][j][c];
    }
    __syncthreads();
    if (grp == 0) {
        const float scale = 1.0f / (float)(T_ * L_);
        const float* mt_ = mg + tile * 2048 + lane;
        float* ob = out + (size_t)b * L_ * L_;
#pragma unroll
        for (int mt = 0; mt < 2; mt++) {
            const int m = mBase + mt * 16 + g;
#pragma unroll
            for (int j = 0; j < 8; j++) {
                const int n = n0 + 8 * j + 2 * q;
                const int i0 = ((mt * 8 + j) * 4) * 32;
                float2 v0, v1;
                v0.x = (acc[mt][j][0] + mt_[i0])      * scale;
                v0.y = (acc[mt][j][1] + mt_[i0 + 32]) * scale;
                v1.x = (acc[mt][j][2] + mt_[i0 + 64]) * scale;
                v1.y = (acc[mt][j][3] + mt_[i0 + 96]) * scale;
                *(float2*)&ob[(size_t)m * L_ + n]       = v0;
                *(float2*)&ob[(size_t)(m + 8) * L_ + n] = v1;
            }
        }
    }
}

extern "C" void kernel_launch(void* const* d_in, const int* in_sizes, int n_in,
                              void* d_out, int out_size)
{
    const float* tgt = (const float*)d_in[0];
    float* out = (float*)d_out;

    cudaFuncSetAttribute(bispectrum_mma_kernel,
                         cudaFuncAttributeMaxDynamicSharedMemorySize, SM_TOTAL);

    bispectrum_mma_kernel<<<256, 256, SM_TOTAL>>>(tgt, out);

    // Reference returns (source, target): echo target after source if the
    // output buffer holds both.
    const long long src_elems = (long long)B_ * L_ * L_;        // 2,097,152
    const long long tgt_elems = (long long)B_ * T_ * L_;        // 65,536
    if ((long long)out_size >= src_elems + tgt_elems) {
        cudaMemcpyAsync(out + src_elems, tgt, sizeof(float) * tgt_elems,
                        cudaMemcpyDeviceToDevice);
    }
}

// round 12
// speedup vs baseline: 9.4247x; 1.1059x over previous
#include <cuda_runtime.h>
#include <cuda_fp16.h>
#include <cstdint>

// Problem constants (target: [B, T, L] float32)
constexpr int B_ = 32;
constexpr int T_ = 8;
constexpr int L_ = 256;

// GEMM formulation per (b, t):
//   S[l, k] = x[k - l]  (0 for k < l)     -- Toeplitz: never materialized.
//   A[m, k] = x[k] * S[m, k]              -- built in registers (hmul2)
//   TM[m, l2] = sum_k A[m,k] * S[l2,k]    -- mma.sync m16n8k16 f16 -> f32
//
// ldmatrix reads directly from 8 shift-copies of the padded fp16 signal
// (copy_s[i] = x_pad[i+s]) at bases E_s = 1168*s (+112 for s=0): every 8-row
// ldmatrix phase is a perfect bank-group permutation (conflict-free).
//
// R12: SYMMETRY. TM[l1,l2] == TM[l2,l1] (integrand symmetric in l1<->l2), so
// compute only the lower-triangle 64x64 tiles (10 of 16 per batch = 62.5% of
// the MMA work) and mirror off-diagonal blocks with scattered stores.
// Grid 320 = 32 b x 10 tri-tiles. CTA: 256 thr, 8 warps = 4 spatial (2x2 of
// 32x32) x 2 t-groups (t 0-3 / 4-7); intra-CTA t-merge via smem.

__device__ __forceinline__ uint32_t smem_u32(const void* p) {
    uint32_t a;
    asm("{ .reg .u64 t; cvta.to.shared.u64 t, %1; cvt.u32.u64 %0, t; }" : "=r"(a) : "l"(p));
    return a;
}
__device__ __forceinline__ uint32_t hmul2(uint32_t a, uint32_t b) {
    uint32_t d;
    asm("mul.rn.f16x2 %0, %1, %2;" : "=r"(d) : "r"(a), "r"(b));
    return d;
}
__device__ __forceinline__ void ldsm4(uint32_t& r0, uint32_t& r1, uint32_t& r2,
                                      uint32_t& r3, uint32_t addr) {
    asm volatile("ldmatrix.sync.aligned.m8n8.x4.shared.b16 {%0,%1,%2,%3}, [%4];"
                 : "=r"(r0), "=r"(r1), "=r"(r2), "=r"(r3) : "r"(addr));
}
__device__ __forceinline__ void mma16816(float* d, const uint32_t* a,
                                         uint32_t b0, uint32_t b1) {
    asm volatile(
        "mma.sync.aligned.m16n8k16.row.col.f32.f16.f16.f32 "
        "{%0,%1,%2,%3}, {%4,%5,%6,%7}, {%8,%9}, {%0,%1,%2,%3};"
        : "+f"(d[0]), "+f"(d[1]), "+f"(d[2]), "+f"(d[3])
        : "r"(a[0]), "r"(a[1]), "r"(a[2]), "r"(a[3]), "r"(b0), "r"(b1));
}

// copy base within a copy set (bytes): E_s = 1168*s + (s==0 ? 112 : 0)
__device__ __forceinline__ uint32_t copy_base(int s) {
    return 1168u * s + (s == 0 ? 112u : 0u);
}

constexpr int COPYSET  = 9216;                    // bytes per t-group copy set
constexpr int SM_MERGE = 2 * COPYSET;             // 18432
constexpr int SM_TOTAL = SM_MERGE + 4 * 1024 * 4; // + 16KB merge = 34816

__global__ __launch_bounds__(256, 2)
void bispectrum_mma_kernel(const float* __restrict__ tgt, float* __restrict__ out)
{
    extern __shared__ __align__(16) unsigned char smb[];
    const uint32_t sB = smem_u32(smb);
    float* mg = (float*)(smb + SM_MERGE);

    const int tid  = threadIdx.x;
    const int w    = tid >> 5;
    const int lane = tid & 31;
    const int g    = lane >> 2;     // 0..7
    const int q    = lane & 3;      // 0..3

    // block -> (batch, lower-triangle tile (i_, j_)), 64x64 tiles, i_ >= j_
    const int bid = blockIdx.x;
    const int b   = bid / 10;
    const int tri = bid - b * 10;
    const int i_  = (tri >= 6) ? 3 : (tri >= 3) ? 2 : (tri >= 1) ? 1 : 0;
    const int j_  = tri - i_ * (i_ + 1) / 2;
    const int m0  = i_ * 64;
    const int n0  = j_ * 64;

    const int sw   = w & 3;                    // spatial warp (2x2)
    const int grp  = w >> 2;                   // t-group (0: t 0-3, 1: t 4-7)
    const int mBase = m0 + 32 * (sw >> 1);
    const int nBase = n0 + 32 * (sw & 1);
    const uint32_t cOff = (uint32_t)grp * COPYSET;

    // zero both copy sets once (left pads stay zero forever)
    for (int i = tid; i < 2 * COPYSET / 4; i += 256)
        *(uint32_t*)(smb + 4 * i) = 0u;

    float acc[2][4][4];
#pragma unroll
    for (int mt = 0; mt < 2; mt++)
#pragma unroll
        for (int j = 0; j < 4; j++)
#pragma unroll
            for (int c = 0; c < 4; c++) acc[mt][j][c] = 0.0f;

    // ---- per-lane ldmatrix base addresses (constant across t, += 32B per kt)
    // row u, col-shift cs (halfs): addr = E(s) + (256 + cs - u - s)*2, s=(-u)&7
    uint32_t aBase[2], bBase[2];
#pragma unroll
    for (int mt = 0; mt < 2; mt++) {
        const int u  = mBase + mt * 16 + (lane & 15);
        const int cs = (lane & 16) ? 8 : 0;
        const int s  = (-u) & 7;
        aBase[mt] = sB + cOff + copy_base(s) + (uint32_t)(256 + cs - u - s) * 2;
    }
#pragma unroll
    for (int nb = 0; nb < 2; nb++) {
        const int u  = nBase + nb * 16 + (lane & 7) + ((lane & 16) ? 8 : 0);
        const int cs = (lane & 8) ? 8 : 0;
        const int s  = (-u) & 7;
        bBase[nb] = sB + cOff + copy_base(s) + (uint32_t)(256 + cs - u - s) * 2;
    }
    // scalar k broadcast from copy 0 of this group's set: half2 at 256+16kt+2q
    const uint32_t xkA = sB + cOff + 112u + 512u + 4u * q;   // += 32 per kt

    for (int tt = 0; tt < 4; tt++) {
        __syncthreads();                   // previous MMA phase done reading copies
        // every thread writes its element into BOTH t-group copy sets
#pragma unroll
        for (int wg = 0; wg < 2; wg++) {
            const __half h = __float2half_rn(
                tgt[(b * T_ + tt + 4 * wg) * L_ + tid]);
#pragma unroll
            for (int s = 0; s < 8; s++)
                *(__half*)(smb + wg * COPYSET + copy_base(s) +
                           (uint32_t)(256 + tid - s) * 2) = h;
        }
        __syncthreads();

        // ---- MMA phase: K = 256 in 16 steps of k16 ----
#pragma unroll 4
        for (int kt = 0; kt < 16; kt++) {
            const uint32_t koff = (uint32_t)kt * 32u;
            uint32_t xk0, xk1;
            asm volatile("ld.shared.b32 %0, [%1];" : "=r"(xk0) : "r"(xkA + koff));
            asm volatile("ld.shared.b32 %0, [%1];" : "=r"(xk1) : "r"(xkA + koff + 16));

            uint32_t Af[2][4];
#pragma unroll
            for (int mt = 0; mt < 2; mt++) {
                uint32_t a0, a1, a2, a3;
                ldsm4(a0, a1, a2, a3, aBase[mt] + koff);
                Af[mt][0] = hmul2(a0, xk0);
                Af[mt][1] = hmul2(a1, xk0);
                Af[mt][2] = hmul2(a2, xk1);
                Af[mt][3] = hmul2(a3, xk1);
            }
#pragma unroll
            for (int nb = 0; nb < 2; nb++) {
                uint32_t b0, b1, b2, b3;
                ldsm4(b0, b1, b2, b3, bBase[nb] + koff);
#pragma unroll
                for (int mt = 0; mt < 2; mt++) {
                    mma16816(acc[mt][2 * nb],     Af[mt], b0, b1);
                    mma16816(acc[mt][2 * nb + 1], Af[mt], b2, b3);
                }
            }
        }
    }

    // ---- merge t-groups (intra-CTA) + epilogue ----
    __syncthreads();
    if (grp == 1) {
        float* mt_ = mg + sw * 1024 + lane;     // stride 32: conflict-free
#pragma unroll
        for (int mt = 0; mt < 2; mt++)
#pragma unroll
            for (int j = 0; j < 4; j++)
#pragma unroll
                for (int c = 0; c < 4; c++)
                    mt_[((mt * 4 + j) * 4 + c) * 32] = acc[mt][j][c];
    }
    __syncthreads();
    if (grp == 0) {
        const float scale = 1.0f / (float)(T_ * L_);
        const float* mt_ = mg + sw * 1024 + lane;
        float* ob = out + (size_t)b * L_ * L_;
        const bool mirror = (i_ != j_);
#pragma unroll
        for (int mt = 0; mt < 2; mt++) {
            const int m = mBase + mt * 16 + g;
#pragma unroll
            for (int j = 0; j < 4; j++) {
                const int n = nBase + 8 * j + 2 * q;
                const int i0 = ((mt * 4 + j) * 4) * 32;
                float2 v0, v1;
                v0.x = (acc[mt][j][0] + mt_[i0])      * scale;
                v0.y = (acc[mt][j][1] + mt_[i0 + 32]) * scale;
                v1.x = (acc[mt][j][2] + mt_[i0 + 64]) * scale;
                v1.y = (acc[mt][j][3] + mt_[i0 + 96]) * scale;
                *(float2*)&ob[(size_t)m * L_ + n]       = v0;
                *(float2*)&ob[(size_t)(m + 8) * L_ + n] = v1;
                if (mirror) {   // TM[n, m] = TM[m, n]
                    ob[(size_t)n * L_ + m]           = v0.x;
                    ob[(size_t)(n + 1) * L_ + m]     = v0.y;
                    ob[(size_t)n * L_ + m + 8]       = v1.x;
                    ob[(size_t)(n + 1) * L_ + m + 8] = v1.y;
                }
            }
        }
    }
}

extern "C" void kernel_launch(void* const* d_in, const int* in_sizes, int n_in,
                              void* d_out, int out_size)
{
    const float* tgt = (const float*)d_in[0];
    float* out = (float*)d_out;

    cudaFuncSetAttribute(bispectrum_mma_kernel,
                         cudaFuncAttributeMaxDynamicSharedMemorySize, SM_TOTAL);

    bispectrum_mma_kernel<<<320, 256, SM_TOTAL>>>(tgt, out);

    // Reference returns (source, target): echo target after source if the
    // output buffer holds both.
    const long long src_elems = (long long)B_ * L_ * L_;        // 2,097,152
    const long long tgt_elems = (long long)B_ * T_ * L_;        // 65,536
    if ((long long)out_size >= src_elems + tgt_elems) {
        cudaMemcpyAsync(out + src_elems, tgt, sizeof(float) * tgt_elems,
                        cudaMemcpyDeviceToDevice);
    }
}

// round 13
// speedup vs baseline: 10.2625x; 1.0889x over previous
#include <cuda_runtime.h>
#include <cuda_fp16.h>
#include <cstdint>

// Problem constants (target: [B, T, L] float32)
constexpr int B_ = 32;
constexpr int T_ = 8;
constexpr int L_ = 256;

// GEMM formulation per (b, t):
//   S[l, k] = x[k - l]  (0 for k < l)     -- Toeplitz: never materialized.
//   A[m, k] = x[k] * S[m, k]              -- built in registers (hmul2)
//   TM[m, l2] = sum_k A[m,k] * S[l2,k]    -- mma.sync m16n8k16 f16 -> f32
//
// ldmatrix reads directly from 8 shift-copies of the padded fp16 signal
// (copy_s[i] = x_pad[i+s]) at bases E_s = 1168*s (+112 for s=0): every 8-row
// ldmatrix phase is a perfect bank-group permutation (conflict-free).
//
// R13: FEED THE PIPE.
//  - ALL 8 t-signals' copy sets preloaded up front (8 x 9KB = 72KB smem);
//    the whole MMA loop (4 tt x 16 kt) runs with ZERO barriers.
//  - Register double-buffering: kt+1 fragments (ldsm/lds) issued before the
//    MMAs of kt, hiding LDSM latency behind tensor work.
// Symmetry (lower-triangle 64x64 tiles, 10/batch) + mirror stores kept from
// R12. Grid 320 = 32 b x 10 tri-tiles; CTA 256 thr = 4 spatial warps (2x2 of
// 32x32) x 2 t-groups; intra-CTA t-merge via smem.

__device__ __forceinline__ uint32_t smem_u32(const void* p) {
    uint32_t a;
    asm("{ .reg .u64 t; cvta.to.shared.u64 t, %1; cvt.u32.u64 %0, t; }" : "=r"(a) : "l"(p));
    return a;
}
__device__ __forceinline__ uint32_t hmul2(uint32_t a, uint32_t b) {
    uint32_t d;
    asm("mul.rn.f16x2 %0, %1, %2;" : "=r"(d) : "r"(a), "r"(b));
    return d;
}
__device__ __forceinline__ void ldsm4(uint32_t& r0, uint32_t& r1, uint32_t& r2,
                                      uint32_t& r3, uint32_t addr) {
    asm volatile("ldmatrix.sync.aligned.m8n8.x4.shared.b16 {%0,%1,%2,%3}, [%4];"
                 : "=r"(r0), "=r"(r1), "=r"(r2), "=r"(r3) : "r"(addr));
}
__device__ __forceinline__ void mma16816(float* d, const uint32_t* a,
                                         uint32_t b0, uint32_t b1) {
    asm volatile(
        "mma.sync.aligned.m16n8k16.row.col.f32.f16.f16.f32 "
        "{%0,%1,%2,%3}, {%4,%5,%6,%7}, {%8,%9}, {%0,%1,%2,%3};"
        : "+f"(d[0]), "+f"(d[1]), "+f"(d[2]), "+f"(d[3])
        : "r"(a[0]), "r"(a[1]), "r"(a[2]), "r"(a[3]), "r"(b0), "r"(b1));
}

// copy base within one copy set (bytes): E_s = 1168*s + (s==0 ? 112 : 0)
__device__ __forceinline__ uint32_t copy_base(int s) {
    return 1168u * s + (s == 0 ? 112u : 0u);
}

constexpr int COPYSET  = 9216;                    // bytes per copy set (one t)
constexpr int SM_MERGE = 8 * COPYSET;             // 73728 (sets 0..7 = t 0..7)
constexpr int SM_TOTAL = SM_MERGE + 4 * 1024 * 4; // + 16KB merge = 90112

__global__ __launch_bounds__(256, 2)
void bispectrum_mma_kernel(const float* __restrict__ tgt, float* __restrict__ out)
{
    extern __shared__ __align__(16) unsigned char smb[];
    const uint32_t sB = smem_u32(smb);
    float* mg = (float*)(smb + SM_MERGE);

    const int tid  = threadIdx.x;
    const int w    = tid >> 5;
    const int lane = tid & 31;
    const int g    = lane >> 2;     // 0..7
    const int q    = lane & 3;      // 0..3

    // block -> (batch, lower-triangle tile (i_, j_)), 64x64 tiles, i_ >= j_
    const int bid = blockIdx.x;
    const int b   = bid / 10;
    const int tri = bid - b * 10;
    const int i_  = (tri >= 6) ? 3 : (tri >= 3) ? 2 : (tri >= 1) ? 1 : 0;
    const int j_  = tri - i_ * (i_ + 1) / 2;
    const int m0  = i_ * 64;
    const int n0  = j_ * 64;

    const int sw   = w & 3;                    // spatial warp (2x2)
    const int grp  = w >> 2;                   // t-group (0: t 0-3, 1: t 4-7)
    const int mBase = m0 + 32 * (sw >> 1);
    const int nBase = n0 + 32 * (sw & 1);
    const uint32_t cOff = (uint32_t)grp * 4 * COPYSET;   // group's first set

    // ---- zero all 8 copy sets, then write all 8 t-signals (one barrier) ----
    for (int i = tid; i < 8 * COPYSET / 4; i += 256)
        *(uint32_t*)(smb + 4 * i) = 0u;
    __syncthreads();
#pragma unroll
    for (int u = 0; u < 8; u++) {              // set u holds t = u
        const __half h = __float2half_rn(tgt[(b * T_ + u) * L_ + tid]);
#pragma unroll
        for (int s = 0; s < 8; s++)
            *(__half*)(smb + u * COPYSET + copy_base(s) +
                       (uint32_t)(256 + tid - s) * 2) = h;
    }
    __syncthreads();

    float acc[2][4][4];
#pragma unroll
    for (int mt = 0; mt < 2; mt++)
#pragma unroll
        for (int j = 0; j < 4; j++)
#pragma unroll
            for (int c = 0; c < 4; c++) acc[mt][j][c] = 0.0f;

    // ---- per-lane ldmatrix base addresses (within a set; add tB + koff) ----
    // row u, col-shift cs (halfs): addr = E(s) + (256 + cs - u - s)*2, s=(-u)&7
    uint32_t aBase[2], bBase[2];
#pragma unroll
    for (int mt = 0; mt < 2; mt++) {
        const int u  = mBase + mt * 16 + (lane & 15);
        const int cs = (lane & 16) ? 8 : 0;
        const int s  = (-u) & 7;
        aBase[mt] = sB + cOff + copy_base(s) + (uint32_t)(256 + cs - u - s) * 2;
    }
#pragma unroll
    for (int nb = 0; nb < 2; nb++) {
        const int u  = nBase + nb * 16 + (lane & 7) + ((lane & 16) ? 8 : 0);
        const int cs = (lane & 8) ? 8 : 0;
        const int s  = (-u) & 7;
        bBase[nb] = sB + cOff + copy_base(s) + (uint32_t)(256 + cs - u - s) * 2;
    }
    const uint32_t xkA = sB + cOff + 112u + 512u + 4u * q;

    // ---- main loop: 4 tt x 16 kt, software-pipelined, no barriers ----
#define LOAD_FRAGS(koff_, AR, BR, XK)                                          \
    do {                                                                       \
        asm volatile("ld.shared.b32 %0, [%1];" : "=r"((XK)[0])                 \
                     : "r"(xkA + (koff_)));                                    \
        asm volatile("ld.shared.b32 %0, [%1];" : "=r"((XK)[1])                 \
                     : "r"(xkA + (koff_) + 16));                               \
        ldsm4((AR)[0], (AR)[1], (AR)[2], (AR)[3], aBase[0] + (koff_));         \
        ldsm4((AR)[4], (AR)[5], (AR)[6], (AR)[7], aBase[1] + (koff_));         \
        ldsm4((BR)[0], (BR)[1], (BR)[2], (BR)[3], bBase[0] + (koff_));         \
        ldsm4((BR)[4], (BR)[5], (BR)[6], (BR)[7], bBase[1] + (koff_));         \
    } while (0)

    for (int tt = 0; tt < 4; tt++) {
        const uint32_t tB = (uint32_t)tt * COPYSET;

        uint32_t ar[2][8], br[2][8], xk[2][2];
        LOAD_FRAGS(tB, ar[0], br[0], xk[0]);

#pragma unroll
        for (int kt = 0; kt < 16; kt++) {
            const int cb = kt & 1;
            const int nx = cb ^ 1;
            if (kt < 15)
                LOAD_FRAGS(tB + (uint32_t)(kt + 1) * 32u, ar[nx], br[nx], xk[nx]);

            uint32_t Af[2][4];
#pragma unroll
            for (int mt = 0; mt < 2; mt++) {
                Af[mt][0] = hmul2(ar[cb][mt * 4 + 0], xk[cb][0]);
                Af[mt][1] = hmul2(ar[cb][mt * 4 + 1], xk[cb][0]);
                Af[mt][2] = hmul2(ar[cb][mt * 4 + 2], xk[cb][1]);
                Af[mt][3] = hmul2(ar[cb][mt * 4 + 3], xk[cb][1]);
            }
#pragma unroll
            for (int nb = 0; nb < 2; nb++)
#pragma unroll
                for (int mt = 0; mt < 2; mt++) {
                    mma16816(acc[mt][2 * nb],     Af[mt], br[cb][nb * 4 + 0], br[cb][nb * 4 + 1]);
                    mma16816(acc[mt][2 * nb + 1], Af[mt], br[cb][nb * 4 + 2], br[cb][nb * 4 + 3]);
                }
        }
    }
#undef LOAD_FRAGS

    // ---- merge t-groups (intra-CTA) + epilogue ----
    __syncthreads();
    if (grp == 1) {
        float* mt_ = mg + sw * 1024 + lane;     // stride 32: conflict-free
#pragma unroll
        for (int mt = 0; mt < 2; mt++)
#pragma unroll
            for (int j = 0; j < 4; j++)
#pragma unroll
                for (int c = 0; c < 4; c++)
                    mt_[((mt * 4 + j) * 4 + c) * 32] = acc[mt][j][c];
    }
    __syncthreads();
    if (grp == 0) {
        const float scale = 1.0f / (float)(T_ * L_);
        const float* mt_ = mg + sw * 1024 + lane;
        float* ob = out + (size_t)b * L_ * L_;
        const bool mirror = (i_ != j_);
#pragma unroll
        for (int mt = 0; mt < 2; mt++) {
            const int m = mBase + mt * 16 + g;
#pragma unroll
            for (int j = 0; j < 4; j++) {
                const int n = nBase + 8 * j + 2 * q;
                const int i0 = ((mt * 4 + j) * 4) * 32;
                float2 v0, v1;
                v0.x = (acc[mt][j][0] + mt_[i0])      * scale;
                v0.y = (acc[mt][j][1] + mt_[i0 + 32]) * scale;
                v1.x = (acc[mt][j][2] + mt_[i0 + 64]) * scale;
                v1.y = (acc[mt][j][3] + mt_[i0 + 96]) * scale;
                *(float2*)&ob[(size_t)m * L_ + n]       = v0;
                *(float2*)&ob[(size_t)(m + 8) * L_ + n] = v1;
                if (mirror) {   // TM[n, m] = TM[m, n]
                    ob[(size_t)n * L_ + m]           = v0.x;
                    ob[(size_t)(n + 1) * L_ + m]     = v0.y;
                    ob[(size_t)n * L_ + m + 8]       = v1.x;
                    ob[(size_t)(n + 1) * L_ + m + 8] = v1.y;
                }
            }
        }
    }
}

extern "C" void kernel_launch(void* const* d_in, const int* in_sizes, int n_in,
                              void* d_out, int out_size)
{
    const float* tgt = (const float*)d_in[0];
    float* out = (float*)d_out;

    cudaFuncSetAttribute(bispectrum_mma_kernel,
                         cudaFuncAttributeMaxDynamicSharedMemorySize, SM_TOTAL);

    bispectrum_mma_kernel<<<320, 256, SM_TOTAL>>>(tgt, out);

    // Reference returns (source, target): echo target after source if the
    // output buffer holds both.
    const long long src_elems = (long long)B_ * L_ * L_;        // 2,097,152
    const long long tgt_elems = (long long)B_ * T_ * L_;        // 65,536
    if ((long long)out_size >= src_elems + tgt_elems) {
        cudaMemcpyAsync(out + src_elems, tgt, sizeof(float) * tgt_elems,
                        cudaMemcpyDeviceToDevice);
    }
}